// round 5
// baseline (speedup 1.0000x reference)
#include <cuda_runtime.h>
#include <cuda_bf16.h>
#include <cstdint>

// out[row][c] = E[row % 8][c] for row < n, else 0.
// Pattern period: 8 rows * 256 fp32 = 8 KB = 512 float4.
// Round-5 experiment: stage pattern in SMEM (32 KB = 4 periods), then stream
// it to GMEM via TMA bulk stores (cp.async.bulk shared->global), bypassing the
// SM store pipe that appears to cap the STG version at ~65% DRAM duty.

#define GROUP_F4 512              // float4 per 8-row group (8 KB)
#define SPAT_GROUPS 4             // groups staged in SMEM (32 KB)
#define FILL_BLOCKS 592           // 148 SMs * 4 CTAs: exactly one wave

__device__ __forceinline__ uint32_t smem_addr_u32(const void* p) {
    uint32_t a;
    asm("{ .reg .u64 t; cvta.to.shared.u64 t, %1; cvt.u32.u64 %0, t; }"
        : "=r"(a) : "l"(p));
    return a;
}

__global__ __launch_bounds__(512, 4)
void rpe_tma_fill_kernel(const float4* __restrict__ E4,   // 512 float4 (8 KB)
                         float4* __restrict__ out4,
                         int num_groups) {
    __shared__ alignas(128) float4 spat[SPAT_GROUPS * GROUP_F4];  // 32 KB

    const int tid = threadIdx.x;              // 0..511
    const float4 val = E4[tid];               // one 8 KB pattern load per CTA
    // Replicate the 8 KB period 4x so bulk ops can be 32 KB each.
    spat[tid]        = val;
    spat[tid + 512]  = val;
    spat[tid + 1024] = val;
    spat[tid + 1536] = val;
    __syncthreads();
    // Order generic-proxy SMEM writes before async-proxy (TMA) reads.
    asm volatile("fence.proxy.async.shared::cta;" ::: "memory");

    // Block-contiguous partition: CTA owns groups [g0, g1).
    const int per_block = (num_groups + gridDim.x - 1) / gridDim.x;
    const int g0 = blockIdx.x * per_block;
    int g1 = g0 + per_block;
    if (g1 > num_groups) g1 = num_groups;

    if (tid == 0 && g1 > g0) {
        const uint32_t src = smem_addr_u32(spat);
        char* dst = (char*)(out4 + (size_t)g0 * GROUP_F4);
        int g = g0;
        // 32 KB bulk stores; TMA engine pulls from SMEM, writes GMEM bursts.
        for (; g + SPAT_GROUPS <= g1; g += SPAT_GROUPS, dst += 32768) {
            asm volatile(
                "cp.async.bulk.global.shared::cta.bulk_group [%0], [%1], %2;"
                :: "l"(dst), "r"(src), "r"(32768) : "memory");
        }
        const int rem = g1 - g;               // 0..3 leftover groups
        if (rem) {
            asm volatile(
                "cp.async.bulk.global.shared::cta.bulk_group [%0], [%1], %2;"
                :: "l"(dst), "r"(src), "r"(rem * 8192) : "memory");
        }
        asm volatile("cp.async.bulk.commit_group;" ::: "memory");
        asm volatile("cp.async.bulk.wait_group 0;" ::: "memory");
    }
}

// Tail: rows [start_row, total_rows). Pattern for row < n, zeros otherwise.
// Not launched for the bench shape (n fills the output with whole groups).
__global__ void rpe_tail_kernel(const float4* __restrict__ E4,
                                float4* __restrict__ out4,
                                int start_row, int total_rows, int n) {
    const int row = start_row + blockIdx.x;   // one block per tail row
    if (row >= total_rows) return;
    const int c = threadIdx.x;                // 0..63 float4 columns
    float4 v;
    if (row < n) {
        v = E4[((row & 7) << 6) | c];
    } else {
        v = make_float4(0.f, 0.f, 0.f, 0.f);
    }
    out4[(size_t)row * 64 + c] = v;
}

extern "C" void kernel_launch(void* const* d_in, const int* in_sizes, int n_in,
                              void* d_out, int out_size) {
    // metadata order: d_in[0] = x (int32, len n; values unused),
    //                 d_in[1] = E_relative_position (float32, 8*256)
    const float4* E4 = (const float4*)d_in[1];
    float4* out4 = (float4*)d_out;

    const int total_rows = out_size / 256;     // 262144
    int n = in_sizes[0];
    if (n > total_rows) n = total_rows;        // never store past d_out
    if (n < 0) n = 0;

    const int full_groups = n / 8;             // 32768 when n == 262144

    if (full_groups > 0) {
        int grid = full_groups < FILL_BLOCKS ? full_groups : FILL_BLOCKS;
        rpe_tma_fill_kernel<<<grid, 512>>>(E4, out4, full_groups);
    }

    const int start_row = full_groups * 8;
    const int tail_rows = total_rows - start_row;
    if (tail_rows > 0) {
        rpe_tail_kernel<<<tail_rows, 64>>>(E4, out4, start_row, total_rows, n);
    }
}